// round 1
// baseline (speedup 1.0000x reference)
#include <cuda_runtime.h>

#define BM 64
#define BN 128
#define BK 16

// ---- scratch (static device globals; no runtime allocation) ----
__device__ __align__(16) float g_Apack[192*288];      // conv0 weights: W0 (128) ++ R0 (64)
__device__ float g_bias0[192];                        // b0 ++ zeros
__device__ float g_y0 [64L*192*4096];                 // conv0 output (gate|hidden|res)
__device__ float g_out0[64L*64*4096];                 // layer0 output = mingru + res (layer1 input)
__device__ float g_y1 [64L*128*4096];                 // conv1 output (gate|hidden)

// ---------------------------------------------------------------
__global__ void pack_kernel(const float* __restrict__ W0,
                            const float* __restrict__ b0,
                            const float* __restrict__ R0) {
    int idx = blockIdx.x * 256 + threadIdx.x;
    if (idx < 192*288) {
        int cout = idx / 288;
        int k    = idx - cout*288;
        g_Apack[idx] = (cout < 128) ? W0[idx] : R0[(cout-128)*288 + k];
    }
    if (idx < 192) g_bias0[idx] = (idx < 128) ? b0[idx] : 0.0f;
}

// Implicit-GEMM 3x3 pad-1 conv over 64x64 images.
//   C[cout, p] = sum_k A[cout, k] * im2col[k, p]   (k = cin*9 + r*3 + s)
// mode 0: A=g_Apack(192x288), bias=g_bias0, X=Xext (input x), Y=g_y0
// mode 1: A=Aext (W1, 128x576), bias=biasext (b1), X=g_out0, Y=g_y1
__global__ __launch_bounds__(256) void conv_gemm(
    const float* __restrict__ Aext, const float* __restrict__ biasext,
    const float* __restrict__ Xext, int mode, int Cin, int K)
{
    const float* A    = (mode == 0) ? g_Apack : Aext;
    const float* bias = (mode == 0) ? g_bias0 : biasext;
    const float* X    = (mode == 0) ? Xext    : g_out0;
    float*       Y    = (mode == 0) ? g_y0    : g_y1;
    const int Cout    = (mode == 0) ? 192     : 128;

    const int img = blockIdx.z;
    const int m0  = blockIdx.y * BM;
    const int n0  = blockIdx.x * BN;
    const float* Ximg = X + (size_t)img * Cin * 4096;

    __shared__ float As[BK][BM];
    __shared__ float Bs[BK][BN];

    const int tid = threadIdx.x;
    const int tm  = tid >> 4;   // 0..15  -> M sub-tile of 4
    const int tn  = tid & 15;   // 0..15  -> N sub-tile of 8

    // A-load mapping: each thread loads one float4 along K
    const int arow = tid >> 2;        // 0..63
    const int aq   = tid & 3;         // 0..3  (k sub-quad)

    // B-load mapping: fixed column, 8 rows per thread
    const int bcol  = tid & 127;      // 0..127
    const int brow0 = tid >> 7;       // 0..1
    const int px = n0 + bcol;
    const int yy0 = px >> 6;
    const int xx0 = px & 63;

    float acc[4][8];
    #pragma unroll
    for (int i = 0; i < 4; i++)
        #pragma unroll
        for (int j = 0; j < 8; j++) acc[i][j] = 0.0f;

    for (int k0 = 0; k0 < K; k0 += BK) {
        // ---- load A tile (64 x 16), store transposed ----
        float4 av = *(const float4*)(A + (size_t)(m0 + arow) * K + k0 + aq * 4);
        As[aq*4 + 0][arow] = av.x;
        As[aq*4 + 1][arow] = av.y;
        As[aq*4 + 2][arow] = av.z;
        As[aq*4 + 3][arow] = av.w;

        // ---- load B tile (16 x 128) via on-the-fly im2col ----
        #pragma unroll
        for (int it = 0; it < 8; it++) {
            int krow = brow0 + it * 2;          // 0..15
            int kk   = k0 + krow;
            int cin  = kk / 9;
            int t9   = kk - cin * 9;
            int r    = t9 / 3 - 1;
            int s    = t9 - (t9/3)*3 - 1;
            int ry = yy0 + r, rx = xx0 + s;
            float v = 0.0f;
            if ((unsigned)ry < 64u && (unsigned)rx < 64u)
                v = Ximg[(size_t)cin * 4096 + ry * 64 + rx];
            Bs[krow][bcol] = v;
        }
        __syncthreads();

        // ---- MAC ----
        #pragma unroll
        for (int kk = 0; kk < BK; kk++) {
            float4 a  = *(const float4*)&As[kk][tm * 4];
            float4 b0v = *(const float4*)&Bs[kk][tn * 8];
            float4 b1v = *(const float4*)&Bs[kk][tn * 8 + 4];
            float av4[4] = {a.x, a.y, a.z, a.w};
            float bv8[8] = {b0v.x, b0v.y, b0v.z, b0v.w, b1v.x, b1v.y, b1v.z, b1v.w};
            #pragma unroll
            for (int i = 0; i < 4; i++)
                #pragma unroll
                for (int j = 0; j < 8; j++)
                    acc[i][j] += av4[i] * bv8[j];
        }
        __syncthreads();
    }

    // ---- epilogue: add bias, store ----
    float* Yimg = Y + (size_t)img * Cout * 4096;
    #pragma unroll
    for (int i = 0; i < 4; i++) {
        int cout = m0 + tm * 4 + i;
        float bv = bias[cout];
        float4 o0 = make_float4(acc[i][0]+bv, acc[i][1]+bv, acc[i][2]+bv, acc[i][3]+bv);
        float4 o1 = make_float4(acc[i][4]+bv, acc[i][5]+bv, acc[i][6]+bv, acc[i][7]+bv);
        float* dst = Yimg + (size_t)cout * 4096 + n0 + tn * 8;
        *(float4*)(dst)     = o0;
        *(float4*)(dst + 4) = o1;
    }
}

// ---------------------------------------------------------------
__device__ __forceinline__ float sigm(float x) {
    return 1.0f / (1.0f + __expf(-x));
}

// Layer-0 scan: h_t = sig(-g)*h + sig(g)*G(hid);  out0 = h + res;  h0 = h(T-1)
__global__ void scan0_kernel(float* __restrict__ d_out) {
    int idx = blockIdx.x * 256 + threadIdx.x;   // B*HID*4096 = 1048576
    int p = idx & 4095;
    int c = (idx >> 12) & 63;
    int b = idx >> 18;
    float h = 0.5f;
    #pragma unroll 1
    for (int t = 0; t < 16; t++) {
        size_t base = ((size_t)(b*16 + t) * 192 + c) * 4096 + p;
        float gate = g_y0[base];
        float hid  = g_y0[base + 64*4096];
        float res  = g_y0[base + 128*4096];
        float z = sigm(gate);
        float a = sigm(-gate);            // exact 1-z, overflow-safe both ways
        float gv = (hid >= 0.0f) ? (hid + 0.5f) : sigm(hid);
        h = a * h + z * gv;
        g_out0[((size_t)(b*16 + t) * 64 + c) * 4096 + p] = h + res;
    }
    d_out[16777216 + ((size_t)b * 64 + c) * 4096 + p] = h;   // h0
}

// Layer-1 scan: input = g_out0 (identity residual); final out + h1
__global__ void scan1_kernel(float* __restrict__ d_out) {
    int idx = blockIdx.x * 256 + threadIdx.x;
    int p = idx & 4095;
    int c = (idx >> 12) & 63;
    int b = idx >> 18;
    float h = 0.5f;
    #pragma unroll 1
    for (int t = 0; t < 16; t++) {
        size_t base = ((size_t)(b*16 + t) * 128 + c) * 4096 + p;
        float gate = g_y1[base];
        float hid  = g_y1[base + 64*4096];
        size_t ioff = ((size_t)(b*16 + t) * 64 + c) * 4096 + p;
        float inp = g_out0[ioff];
        float z = sigm(gate);
        float a = sigm(-gate);
        float gv = (hid >= 0.0f) ? (hid + 0.5f) : sigm(hid);
        h = a * h + z * gv;
        d_out[ioff] = h + inp;            // final output, same indexing as out0
    }
    d_out[17825792 + ((size_t)b * 64 + c) * 4096 + p] = h;   // h1
}

// ---------------------------------------------------------------
extern "C" void kernel_launch(void* const* d_in, const int* in_sizes, int n_in,
                              void* d_out, int out_size) {
    const float* x  = (const float*)d_in[0];
    const float* W0 = (const float*)d_in[1];
    const float* b0 = (const float*)d_in[2];
    const float* R0 = (const float*)d_in[3];
    const float* W1 = (const float*)d_in[4];
    const float* b1 = (const float*)d_in[5];
    float* out = (float*)d_out;

    // pack conv0 weights (W0 ++ R0) + bias
    pack_kernel<<<(192*288 + 255)/256, 256>>>(W0, b0, R0);

    // conv0: 192 x 288 GEMM per image
    conv_gemm<<<dim3(32, 3, 64), 256>>>(nullptr, nullptr, x, /*mode=*/0, /*Cin=*/32, /*K=*/288);

    // layer-0 scan (+ residual add, h0)
    scan0_kernel<<<4096, 256>>>(out);

    // conv1: 128 x 576 GEMM per image on g_out0
    conv_gemm<<<dim3(32, 2, 64), 256>>>(W1, b1, nullptr, /*mode=*/1, /*Cin=*/64, /*K=*/576);

    // layer-1 scan (+ identity residual, final out, h1)
    scan1_kernel<<<4096, 256>>>(out);
}

// round 3
// speedup vs baseline: 2.7711x; 2.7711x over previous
#include <cuda_runtime.h>
#include <cstdint>

// ================= scratch (static device globals) =================
__device__ __align__(16) float g_xt   [64L*4096*32];   // x transposed [img][p][cin]
__device__ __align__(16) float g_y0t  [64L*4096*192];  // conv0 out [img][p][cout] (gate|hid|res)
__device__ __align__(16) float g_out0t[64L*4096*64];   // layer0 out [img][p][c]
__device__ __align__(16) float g_y1t  [64L*4096*128];  // conv1 out [img][p][cout] (gate|hid)
__device__ __align__(16) float g_A0   [2*9*128*32];    // conv0 weights [tile][tap][row128][cin32], tf32-rounded
__device__ __align__(16) float g_A1   [18*128*32];     // conv1 weights [chunk][row128][cin32], tf32-rounded

// ================= helpers =================
static __device__ __forceinline__ uint32_t s2u(const void* p) {
    uint32_t a;
    asm("{ .reg .u64 t; cvta.to.shared.u64 t, %1; cvt.u32.u64 %0, t; }" : "=r"(a) : "l"(p));
    return a;
}
static __device__ __forceinline__ uint32_t f2tf(float f) {
    uint32_t u;
    asm("cvt.rna.tf32.f32 %0, %1;" : "=r"(u) : "f"(f));
    return u;
}
static __device__ __forceinline__ void cp16(uint32_t daddr, const void* gptr, bool pred) {
    int sz = pred ? 16 : 0;
    asm volatile("cp.async.ca.shared.global [%0], [%1], 16, %2;"
                 :: "r"(daddr), "l"(gptr), "r"(sz));
}
static __device__ __forceinline__ void mma_tf32(float& d0, float& d1, float& d2, float& d3,
                                                uint32_t a0, uint32_t a1, uint32_t a2, uint32_t a3,
                                                uint32_t b0, uint32_t b1) {
    asm volatile("mma.sync.aligned.m16n8k8.row.col.f32.tf32.tf32.f32 "
                 "{%0,%1,%2,%3}, {%4,%5,%6,%7}, {%8,%9}, {%0,%1,%2,%3};"
                 : "+f"(d0), "+f"(d1), "+f"(d2), "+f"(d3)
                 : "r"(a0), "r"(a1), "r"(a2), "r"(a3), "r"(b0), "r"(b1));
}

// ================= pre-processing =================
// x [img][32][4096] -> g_xt [img][p][32]
__global__ void transpose_x(const float* __restrict__ x) {
    __shared__ float s[32][137];
    const int img = blockIdx.y, p0 = blockIdx.x * 128, t = threadIdx.x;
    const int c8 = t >> 5, pq = t & 31;
    for (int cc = c8; cc < 32; cc += 8) {
        float4 v = *(const float4*)(x + ((size_t)img * 32 + cc) * 4096 + p0 + pq * 4);
        s[cc][pq*4+0] = v.x; s[cc][pq*4+1] = v.y; s[cc][pq*4+2] = v.z; s[cc][pq*4+3] = v.w;
    }
    __syncthreads();
    const int pl = t >> 3, cq = t & 7;
    for (int pp = pl; pp < 128; pp += 32) {
        float4 v;
        v.x = s[cq*4+0][pp]; v.y = s[cq*4+1][pp]; v.z = s[cq*4+2][pp]; v.w = s[cq*4+3][pp];
        *(float4*)(g_xt + ((size_t)img * 4096 + p0 + pp) * 32 + cq * 4) = v;
    }
}

// conv0 weights (W0 ++ R0) -> [tile][tap][row][cin], tf32-rounded. tile1 rows >=64 are zero.
__global__ void packA0(const float* __restrict__ W0, const float* __restrict__ R0) {
    int idx = blockIdx.x * 256 + threadIdx.x;      // 73728
    if (idx >= 73728) return;
    int tile = idx / 36864;
    int rem  = idx - tile * 36864;
    int ck   = rem >> 12;            // tap 0..8
    int row  = (rem >> 5) & 127;
    int cin  = rem & 31;
    int cout = tile * 128 + row;
    float v = 0.0f;
    if (cout < 128)      v = W0[cout * 288 + cin * 9 + ck];
    else if (cout < 192) v = R0[(cout - 128) * 288 + cin * 9 + ck];
    g_A0[idx] = __uint_as_float(f2tf(v));
}
__global__ void packA1(const float* __restrict__ W1) {
    int idx = blockIdx.x * 256 + threadIdx.x;      // 73728
    if (idx >= 73728) return;
    int ck  = idx >> 12;             // chunk 0..17 : tap = ck>>1, cin half = ck&1
    int row = (idx >> 5) & 127;
    int cl  = idx & 31;
    int tap = ck >> 1;
    int cin = ((ck & 1) << 5) + cl;
    g_A1[idx] = __uint_as_float(f2tf(W1[row * 576 + cin * 9 + tap]));
}

// ================= tf32 HMMA implicit-GEMM conv =================
// CTA: 128 couts x 128 pixels, K-chunks of 32. 8 warps (2m x 4n), warp 64x32 via m16n8k8.
#define PITCH 36
#define ATILE_BYTES (128*PITCH*4)     // 18432
#define BUF_BYTES   (2*ATILE_BYTES)   // 36864 (A + B)
#define SMEM_BYTES  (2*BUF_BYTES)     // 73728

__global__ __launch_bounds__(256) void conv_tc(int mode, const float* __restrict__ bias) {
    extern __shared__ __align__(16) char smem[];
    const uint32_t sb = s2u(smem);
    const int tid  = threadIdx.x;
    const int lane = tid & 31;
    const int wid  = tid >> 5;
    const int wm   = wid >> 2;       // 0..1
    const int wn   = wid & 3;        // 0..3

    const float* Xt; float* Y; const float* Aw; int C, NCH, CoutS;
    if (mode == 0) { Xt = g_xt;    Y = g_y0t; Aw = g_A0 + blockIdx.y * 36864; C = 32; NCH = 9;  CoutS = 192; }
    else           { Xt = g_out0t; Y = g_y1t; Aw = g_A1;                      C = 64; NCH = 18; CoutS = 128; }
    const int m0  = blockIdx.y * 128;
    const int img = blockIdx.z;
    const int n0  = blockIdx.x * 128;
    const float* Ximg = Xt + (size_t)img * 4096 * C;

    // per-thread load mapping: 4 float4 for A, 4 for B
    const int lrow = tid >> 1;            // 0..127 (row / pixel), 2 float4 each, x2 iters
    const int lq   = (tid & 1) * 2;       // starting q (0 or 2), q and q+... iterate

    float acc[4][4][4];
    #pragma unroll
    for (int a = 0; a < 4; a++)
        #pragma unroll
        for (int b = 0; b < 4; b++)
            #pragma unroll
            for (int c = 0; c < 4; c++) acc[a][b][c] = 0.0f;

    // ---- prefetch helper (inlined via lambda-free macro style) ----
    auto prefetch = [&](int ck, int buf) {
        const uint32_t abase = sb + buf * BUF_BYTES;
        const uint32_t bbase = abase + ATILE_BYTES;
        // A: rows 0..127, 8 float4 per row; thread does rows lrow with q = lq, lq+1 then rows +? (4 loads)
        const float* asrc = Aw + ck * 4096;
        #pragma unroll
        for (int i = 0; i < 2; i++) {
            int q = lq + i;                               // 0..3
            cp16(abase + (lrow * PITCH + q * 4) * 4, asrc + lrow * 32 + q * 4, true);
            int q2 = q + 4;                               // 4..7
            // second half of row handled by q2 below in same loop to make 4 total
            cp16(abase + (lrow * PITCH + q2 * 4) * 4, asrc + lrow * 32 + q2 * 4, true);
        }
        // B: pixels 0..127, 8 float4 per pixel
        const int tap  = (C == 32) ? ck : (ck >> 1);
        const int cin0 = (C == 32) ? 0  : ((ck & 1) << 5);
        const int r = tap / 3 - 1;
        const int s = tap - (tap / 3) * 3 - 1;
        const int d = r * 64 + s;
        const int P = n0 + lrow;
        const int y = P >> 6, x = P & 63;
        const bool ok = ((unsigned)(y + r) < 64u) && ((unsigned)(x + s) < 64u);
        const float* bsrc = Ximg + (long)(P + d) * C + cin0;
        #pragma unroll
        for (int i = 0; i < 2; i++) {
            int q = lq + i;
            cp16(bbase + (lrow * PITCH + q * 4) * 4, bsrc + q * 4, ok);
            int q2 = q + 4;
            cp16(bbase + (lrow * PITCH + q2 * 4) * 4, bsrc + q2 * 4, ok);
        }
    };

    prefetch(0, 0);
    asm volatile("cp.async.commit_group;" ::: "memory");

    for (int ck = 0; ck < NCH; ck++) {
        const int buf = ck & 1;
        if (ck + 1 < NCH) prefetch(ck + 1, buf ^ 1);
        asm volatile("cp.async.commit_group;" ::: "memory");
        asm volatile("cp.async.wait_group 1;" ::: "memory");
        __syncthreads();

        const uint32_t* Asu = (const uint32_t*)(smem + buf * BUF_BYTES);
        const float*    Bsf = (const float*)(smem + buf * BUF_BYTES + ATILE_BYTES);
        const int rb = wm * 64 + (lane >> 2);
        const int ct = lane & 3;
        #pragma unroll
        for (int ks = 0; ks < 4; ks++) {
            const int c = ks * 8 + ct;
            uint32_t afr[4][4];
            #pragma unroll
            for (int mf = 0; mf < 4; mf++) {
                const int base = (rb + mf * 16) * PITCH + c;
                afr[mf][0] = Asu[base];
                afr[mf][1] = Asu[base + 8 * PITCH];
                afr[mf][2] = Asu[base + 4];
                afr[mf][3] = Asu[base + 8 * PITCH + 4];
            }
            #pragma unroll
            for (int nf = 0; nf < 4; nf++) {
                const int nrow = wn * 32 + nf * 8 + (lane >> 2);
                const uint32_t b0 = f2tf(Bsf[nrow * PITCH + c]);
                const uint32_t b1 = f2tf(Bsf[nrow * PITCH + c + 4]);
                #pragma unroll
                for (int mf = 0; mf < 4; mf++)
                    mma_tf32(acc[mf][nf][0], acc[mf][nf][1], acc[mf][nf][2], acc[mf][nf][3],
                             afr[mf][0], afr[mf][1], afr[mf][2], afr[mf][3], b0, b1);
            }
        }
        __syncthreads();
    }

    // ---- epilogue: acc -> Y [img][pixel][cout], + bias ----
    float* Yimg = Y + (size_t)img * 4096 * CoutS;
    #pragma unroll
    for (int mf = 0; mf < 4; mf++) {
        const int r  = m0 + wm * 64 + mf * 16 + (lane >> 2);
        if (r >= CoutS) continue;
        const float bv  = (r < 128) ? bias[r] : 0.0f;
        #pragma unroll
        for (int nf = 0; nf < 4; nf++) {
            const int cc = n0 + wn * 32 + nf * 8 + (lane & 3) * 2;
            Yimg[(size_t)cc       * CoutS + r]     = acc[mf][nf][0] + bv;
            Yimg[(size_t)(cc + 1) * CoutS + r]     = acc[mf][nf][1] + bv;
            Yimg[(size_t)cc       * CoutS + r + 8] = acc[mf][nf][2] + bv;
            Yimg[(size_t)(cc + 1) * CoutS + r + 8] = acc[mf][nf][3] + bv;
        }
    }
}

// ================= scans =================
static __device__ __forceinline__ float sigm(float x) { return 1.0f / (1.0f + __expf(-x)); }

// layer0: reads y0t [img][p][192], writes out0t [img][p][64] + h0 to d_out
__global__ void scan0_kernel(float* __restrict__ out) {
    const int g = blockIdx.x * 256 + threadIdx.x;    // 1,048,576
    const int c = g & 63;
    const int p = (g >> 6) & 4095;
    const int b = g >> 18;
    float h = 0.5f;
    #pragma unroll 1
    for (int t = 0; t < 16; t++) {
        const size_t base = ((size_t)(b * 16 + t) * 4096 + p) * 192;
        const float gate = g_y0t[base + c];
        const float hid  = g_y0t[base + 64 + c];
        const float res  = g_y0t[base + 128 + c];
        const float z  = sigm(gate);
        const float a  = sigm(-gate);
        const float gv = (hid >= 0.0f) ? (hid + 0.5f) : sigm(hid);
        h = a * h + z * gv;
        g_out0t[((size_t)(b * 16 + t) * 4096 + p) * 64 + c] = h + res;
    }
    out[16777216 + ((size_t)b * 64 + c) * 4096 + p] = h;   // h0 [b][c][p]
}

// layer1: reads y1t [img][p][128] + out0t; writes final out [img][c][p] + h1
__global__ void scan1_kernel(float* __restrict__ out) {
    __shared__ __align__(16) float st[64][68];
    const int t  = threadIdx.x;
    const int pb = blockIdx.x;        // 0..63
    const int b  = blockIdx.y;        // 0..3
    const int p0 = pb * 64;
    const int pl = t >> 2, qb = t & 3;
    const int co = t >> 2, pq = t & 3;
    float h[16];
    #pragma unroll
    for (int i = 0; i < 16; i++) h[i] = 0.5f;

    #pragma unroll 1
    for (int ts = 0; ts < 16; ts++) {
        const int img = b * 16 + ts;
        const size_t rb = (size_t)img * 4096 + p0 + pl;
        #pragma unroll
        for (int j = 0; j < 4; j++) {
            const int c0 = qb * 4 + 16 * j;
            const float4 g4 = *(const float4*)(g_y1t   + rb * 128 + c0);
            const float4 d4 = *(const float4*)(g_y1t   + rb * 128 + 64 + c0);
            const float4 i4 = *(const float4*)(g_out0t + rb * 64 + c0);
            const float gv4[4] = {g4.x, g4.y, g4.z, g4.w};
            const float dv4[4] = {d4.x, d4.y, d4.z, d4.w};
            const float iv4[4] = {i4.x, i4.y, i4.z, i4.w};
            #pragma unroll
            for (int e = 0; e < 4; e++) {
                const float z  = sigm(gv4[e]);
                const float a  = sigm(-gv4[e]);
                const float gg = (dv4[e] >= 0.0f) ? (dv4[e] + 0.5f) : sigm(dv4[e]);
                float hh = a * h[j * 4 + e] + z * gg;
                h[j * 4 + e] = hh;
                st[c0 + e][pl] = hh + iv4[e];
            }
        }
        __syncthreads();
        #pragma unroll
        for (int i = 0; i < 4; i++) {
            const float4 v = *(const float4*)&st[co][pq * 16 + 4 * i];
            *(float4*)(out + ((size_t)img * 64 + co) * 4096 + p0 + pq * 16 + 4 * i) = v;
        }
        __syncthreads();
    }
    // h1 via same transpose
    #pragma unroll
    for (int j = 0; j < 4; j++)
        #pragma unroll
        for (int e = 0; e < 4; e++)
            st[qb * 4 + 16 * j + e][pl] = h[j * 4 + e];
    __syncthreads();
    #pragma unroll
    for (int i = 0; i < 4; i++) {
        const float4 v = *(const float4*)&st[co][pq * 16 + 4 * i];
        *(float4*)(out + 17825792 + ((size_t)b * 64 + co) * 4096 + p0 + pq * 16 + 4 * i) = v;
    }
}

// ================= launch =================
extern "C" void kernel_launch(void* const* d_in, const int* in_sizes, int n_in,
                              void* d_out, int out_size) {
    const float* x  = (const float*)d_in[0];
    const float* W0 = (const float*)d_in[1];
    const float* b0 = (const float*)d_in[2];
    const float* R0 = (const float*)d_in[3];
    const float* W1 = (const float*)d_in[4];
    const float* b1 = (const float*)d_in[5];
    float* out = (float*)d_out;

    static int smem_set = 0;
    if (!smem_set) {
        cudaFuncSetAttribute(conv_tc, cudaFuncAttributeMaxDynamicSharedMemorySize, SMEM_BYTES);
        smem_set = 1;
    }

    transpose_x<<<dim3(32, 64), 256>>>(x);
    packA0<<<288, 256>>>(W0, R0);
    packA1<<<288, 256>>>(W1);

    conv_tc<<<dim3(32, 2, 64), 256, SMEM_BYTES>>>(0, b0);
    scan0_kernel<<<4096, 256>>>(out);
    conv_tc<<<dim3(32, 1, 64), 256, SMEM_BYTES>>>(1, b1);
    scan1_kernel<<<dim3(64, 4), 256>>>(out);
}